// round 1
// baseline (speedup 1.0000x reference)
#include <cuda_runtime.h>
#include <math.h>

// ============================================================================
// GCN decoder chain, fp32 baseline:
//   T1 = z_igae @ w3                      [10000,256]
//   Z1 = tanh(adj @ T1)                   [10000,256]
//   T2 = Z1 @ w4                          [10000,128]
//   Z2 = tanh(adj @ T2)                   [10000,128]
//   T3 = Z2 @ w5                          [10000,500]
//   z_hat = adj @ T3                      [10000,500]   -> d_out[0 .. 5e6)
//   z_hat_adj = sigmoid(z_hat @ z_hat^T)  [10000,10000] -> d_out[5e6 .. 105e6)
// ============================================================================

#define NROWS 10000
#define BM 128
#define BN 128
#define BK 8
#define TM 8
#define TN 8
#define NTHREADS 256

// Scratch (allocation-free rule: static __device__ globals).
__device__ float g_bufA[NROWS * 500];
__device__ float g_bufB[NROWS * 500];

// ACT: 0 = none, 1 = tanh, 2 = sigmoid
// TRANS_B: 0 -> B is [K,N] row-major (NN). 1 -> B is [N,K] row-major (NT).
template <int TRANS_B, int ACT>
__global__ __launch_bounds__(NTHREADS) void gemm_kernel(
    const float* __restrict__ A, const float* __restrict__ B,
    float* __restrict__ C, int M, int N, int K)
{
    __shared__ float As[BK][BM];
    __shared__ float Bs[BK][BN];

    const int t  = threadIdx.x;
    const int m0 = blockIdx.y * BM;
    const int n0 = blockIdx.x * BN;

    // A tile loader: 128 rows x 8 cols, one float4 per thread.
    const int ar = t >> 1;          // 0..127
    const int ac = (t & 1) * 4;     // 0 or 4

    // B tile loader indices.
    const int br_nn = t >> 5;           // 0..7   (k within tile)
    const int bc_nn = (t & 31) * 4;     // 0..124 (n within tile)
    const int br_nt = t >> 1;           // 0..127 (n within tile)
    const int bc_nt = (t & 1) * 4;      // 0 or 4 (k within tile)

    const int ty = t >> 4;   // 0..15, m direction
    const int tx = t & 15;   // 0..15, n direction

    float acc[TM][TN];
    #pragma unroll
    for (int i = 0; i < TM; i++)
        #pragma unroll
        for (int j = 0; j < TN; j++)
            acc[i][j] = 0.0f;

    for (int k0 = 0; k0 < K; k0 += BK) {
        // ---- load A tile (transposed into As[k][m]) ----
        {
            float4 av = make_float4(0.f, 0.f, 0.f, 0.f);
            const int arow = m0 + ar;
            const int acol = k0 + ac;
            // K is always a multiple of 4 here (20,128,256,500,10000), so
            // acol < K implies acol+3 < K; float4 is 16B-aligned.
            if (arow < M && acol < K)
                av = *reinterpret_cast<const float4*>(A + (size_t)arow * K + acol);
            As[ac + 0][ar] = av.x;
            As[ac + 1][ar] = av.y;
            As[ac + 2][ar] = av.z;
            As[ac + 3][ar] = av.w;
        }
        // ---- load B tile ----
        if (TRANS_B) {
            float4 bv = make_float4(0.f, 0.f, 0.f, 0.f);
            const int brow = n0 + br_nt;   // row of B[N,K]
            const int bcol = k0 + bc_nt;   // col (k)
            if (brow < N && bcol < K)
                bv = *reinterpret_cast<const float4*>(B + (size_t)brow * K + bcol);
            Bs[bc_nt + 0][br_nt] = bv.x;
            Bs[bc_nt + 1][br_nt] = bv.y;
            Bs[bc_nt + 2][br_nt] = bv.z;
            Bs[bc_nt + 3][br_nt] = bv.w;
        } else {
            float4 bv = make_float4(0.f, 0.f, 0.f, 0.f);
            const int brow = k0 + br_nn;   // row of B[K,N] (k)
            const int bcol = n0 + bc_nn;   // col (n)
            if (brow < K && bcol < N)      // N multiple of 4 -> bcol<N ok for float4
                bv = *reinterpret_cast<const float4*>(B + (size_t)brow * N + bcol);
            *reinterpret_cast<float4*>(&Bs[br_nn][bc_nn]) = bv;
        }
        __syncthreads();

        // ---- compute ----
        #pragma unroll
        for (int kk = 0; kk < BK; kk++) {
            float a[TM], b[TN];
            *reinterpret_cast<float4*>(&a[0]) =
                *reinterpret_cast<const float4*>(&As[kk][ty * TM]);
            *reinterpret_cast<float4*>(&a[4]) =
                *reinterpret_cast<const float4*>(&As[kk][ty * TM + 4]);
            *reinterpret_cast<float4*>(&b[0]) =
                *reinterpret_cast<const float4*>(&Bs[kk][tx * TN]);
            *reinterpret_cast<float4*>(&b[4]) =
                *reinterpret_cast<const float4*>(&Bs[kk][tx * TN + 4]);
            #pragma unroll
            for (int i = 0; i < TM; i++)
                #pragma unroll
                for (int j = 0; j < TN; j++)
                    acc[i][j] = fmaf(a[i], b[j], acc[i][j]);
        }
        __syncthreads();
    }

    // ---- epilogue ----
    #pragma unroll
    for (int i = 0; i < TM; i++) {
        const int m = m0 + ty * TM + i;
        if (m >= M) continue;
        #pragma unroll
        for (int j = 0; j < TN; j++) {
            const int n = n0 + tx * TN + j;
            if (n >= N) continue;
            float v = acc[i][j];
            if (ACT == 1)      v = tanhf(v);
            else if (ACT == 2) v = 1.0f / (1.0f + expf(-v));
            C[(size_t)m * N + n] = v;
        }
    }
}

static inline void launch_gemm(const float* A, const float* B, float* C,
                               int M, int N, int K, int trans_b, int act)
{
    dim3 grid((N + BN - 1) / BN, (M + BM - 1) / BM);
    dim3 block(NTHREADS);
    if (!trans_b) {
        if (act == 0)      gemm_kernel<0, 0><<<grid, block>>>(A, B, C, M, N, K);
        else if (act == 1) gemm_kernel<0, 1><<<grid, block>>>(A, B, C, M, N, K);
        else               gemm_kernel<0, 2><<<grid, block>>>(A, B, C, M, N, K);
    } else {
        if (act == 0)      gemm_kernel<1, 0><<<grid, block>>>(A, B, C, M, N, K);
        else if (act == 1) gemm_kernel<1, 1><<<grid, block>>>(A, B, C, M, N, K);
        else               gemm_kernel<1, 2><<<grid, block>>>(A, B, C, M, N, K);
    }
}

extern "C" void kernel_launch(void* const* d_in, const int* in_sizes, int n_in,
                              void* d_out, int out_size)
{
    const float* z_igae = (const float*)d_in[0];  // [10000, 20]
    const float* adj    = (const float*)d_in[1];  // [10000, 10000]
    const float* w3     = (const float*)d_in[2];  // [20, 256]
    const float* w4     = (const float*)d_in[3];  // [256, 128]
    const float* w5     = (const float*)d_in[4];  // [128, 500]

    float* out      = (float*)d_out;
    float* z_hat    = out;                         // [10000, 500]
    float* z_hatadj = out + (size_t)NROWS * 500;   // [10000, 10000]

    float *bufA = nullptr, *bufB = nullptr;
    cudaGetSymbolAddress((void**)&bufA, g_bufA);
    cudaGetSymbolAddress((void**)&bufB, g_bufB);

    // T1 = z_igae @ w3
    launch_gemm(z_igae, w3, bufB, NROWS, 256, 20,   0, 0);
    // Z1 = tanh(adj @ T1)
    launch_gemm(adj,    bufB, bufA, NROWS, 256, NROWS, 0, 1);
    // T2 = Z1 @ w4
    launch_gemm(bufA,   w4, bufB, NROWS, 128, 256,  0, 0);
    // Z2 = tanh(adj @ T2)
    launch_gemm(adj,    bufB, bufA, NROWS, 128, NROWS, 0, 1);
    // T3 = Z2 @ w5
    launch_gemm(bufA,   w5, bufB, NROWS, 500, 128,  0, 0);
    // z_hat = adj @ T3
    launch_gemm(adj,    bufB, z_hat, NROWS, 500, NROWS, 0, 0);
    // z_hat_adj = sigmoid(z_hat @ z_hat^T)
    launch_gemm(z_hat,  z_hat, z_hatadj, NROWS, NROWS, 500, 1, 2);
}

// round 2
// speedup vs baseline: 2.1322x; 2.1322x over previous
#include <cuda_runtime.h>
#include <cuda_bf16.h>
#include <math.h>
#include <stdint.h>

// ============================================================================
// GCN decoder chain. Big GEMMs (adj@X, z_hat@z_hat^T) on tensor cores via
// mma.sync m16n8k16 bf16 with 2-term bf16 splitting (hi+lo) for fp32-class
// accuracy: C = Ahi*Bhi + Ahi*Blo + Alo*Bhi   (lo*lo dropped, ~2^-16 rel).
// Small X@W GEMMs stay fp32 SIMT.
// ============================================================================

#define NROWS 10000
#define ADJ_N 100000000LL

// ---------------- scratch (static __device__, allocation-free) -------------
__device__ __nv_bfloat16 g_adj_hi[100000000];
__device__ __nv_bfloat16 g_adj_lo[100000000];
__device__ __nv_bfloat16 g_bt_hi[500 * 10000];   // transposed split of T (B^T)
__device__ __nv_bfloat16 g_bt_lo[500 * 10000];
__device__ __nv_bfloat16 g_zh_hi[10000 * 512];   // z_hat split, K padded to 512
__device__ __nv_bfloat16 g_zh_lo[10000 * 512];   // (pad cols stay zero forever)
__device__ float g_f1[10000 * 512];
__device__ float g_f2[10000 * 512];

// ---------------- fp32 split helpers ---------------------------------------
__device__ __forceinline__ void split2(float x, __nv_bfloat16& h, __nv_bfloat16& l) {
    h = __float2bfloat16(x);
    l = __float2bfloat16(x - __bfloat162float(h));
}

// ---------------- adj split (elementwise, float4) ---------------------------
__global__ void split_vec4(const float* __restrict__ x,
                           __nv_bfloat16* __restrict__ hi,
                           __nv_bfloat16* __restrict__ lo, int n4)
{
    int i = blockIdx.x * blockDim.x + threadIdx.x;
    if (i >= n4) return;
    float4 v = reinterpret_cast<const float4*>(x)[i];
    __nv_bfloat16 h0, h1, h2, h3, l0, l1, l2, l3;
    split2(v.x, h0, l0); split2(v.y, h1, l1);
    split2(v.z, h2, l2); split2(v.w, h3, l3);
    reinterpret_cast<__nv_bfloat162*>(hi)[2 * i + 0] = __halves2bfloat162(h0, h1);
    reinterpret_cast<__nv_bfloat162*>(hi)[2 * i + 1] = __halves2bfloat162(h2, h3);
    reinterpret_cast<__nv_bfloat162*>(lo)[2 * i + 0] = __halves2bfloat162(l0, l1);
    reinterpret_cast<__nv_bfloat162*>(lo)[2 * i + 1] = __halves2bfloat162(l2, l3);
}

// ---------------- transpose + split: T[Kt,Nn] fp32 -> hi/lo [Nn,Kt] bf16 ----
__global__ void tsplit_kernel(const float* __restrict__ T, int Kt, int Nn,
                              __nv_bfloat16* __restrict__ hi,
                              __nv_bfloat16* __restrict__ lo)
{
    __shared__ float sm[32][33];
    int tx = threadIdx.x & 31;
    int ty = threadIdx.x >> 5;          // 0..7
    int k0 = blockIdx.y * 32;
    int n0 = blockIdx.x * 32;
    #pragma unroll
    for (int r = 0; r < 4; r++) {
        int row = k0 + ty + r * 8;
        int col = n0 + tx;
        sm[ty + r * 8][tx] = (row < Kt && col < Nn) ? T[(size_t)row * Nn + col] : 0.0f;
    }
    __syncthreads();
    #pragma unroll
    for (int r = 0; r < 4; r++) {
        int n = n0 + ty + r * 8;
        int k = k0 + tx;
        if (n < Nn && k < Kt) {
            float v = sm[tx][ty + r * 8];
            __nv_bfloat16 h, l;
            split2(v, h, l);
            hi[(size_t)n * Kt + k] = h;
            lo[(size_t)n * Kt + k] = l;
        }
    }
}

// ---------------- tensor-core split-bf16 GEMM -------------------------------
// C[M,N] = A[M,K] @ B[N,K]^T  (both operands given as hi/lo bf16 pairs,
// B in row-major [N,K] i.e. k-contiguous).
// ACT: 0 none, 1 tanh, 2 sigmoid. WSPLIT: also write bf16 split of C.

#define SSTR 40   // smem k-stride (bf16 elems), conflict-free frag loads

__device__ __forceinline__ void mma16816(float c[4], const uint32_t a[4],
                                         const uint32_t b[2])
{
    asm volatile(
        "mma.sync.aligned.m16n8k16.row.col.f32.bf16.bf16.f32 "
        "{%0,%1,%2,%3}, {%4,%5,%6,%7}, {%8,%9}, {%0,%1,%2,%3};"
        : "+f"(c[0]), "+f"(c[1]), "+f"(c[2]), "+f"(c[3])
        : "r"(a[0]), "r"(a[1]), "r"(a[2]), "r"(a[3]), "r"(b[0]), "r"(b[1]));
}

template <int ACT, int WSPLIT>
__global__ __launch_bounds__(256, 1) void mma_gemm(
    const __nv_bfloat16* __restrict__ Ahi, const __nv_bfloat16* __restrict__ Alo, int lda,
    const __nv_bfloat16* __restrict__ Bhi, const __nv_bfloat16* __restrict__ Blo, int ldb,
    float* __restrict__ C, int ldc,
    __nv_bfloat16* __restrict__ Shi, __nv_bfloat16* __restrict__ Slo, int lds,
    int M, int N, int K)
{
    __shared__ alignas(16) __nv_bfloat16 AsH[128 * SSTR];
    __shared__ alignas(16) __nv_bfloat16 AsL[128 * SSTR];
    __shared__ alignas(16) __nv_bfloat16 BsH[128 * SSTR];
    __shared__ alignas(16) __nv_bfloat16 BsL[128 * SSTR];

    const int t    = threadIdx.x;
    const int lane = t & 31;
    const int wid  = t >> 5;
    const int wm   = (wid >> 2) * 64;   // warp m offset within CTA tile
    const int wn   = (wid & 3) * 32;    // warp n offset
    const int g    = lane >> 2;         // group id 0..7
    const int tg   = lane & 3;          // thread-in-group 0..3

    const int m0 = blockIdx.y * 128;
    const int n0 = blockIdx.x * 128;

    float acc[4][4][4];
    #pragma unroll
    for (int i = 0; i < 4; i++)
        #pragma unroll
        for (int j = 0; j < 4; j++)
            #pragma unroll
            for (int c = 0; c < 4; c++) acc[i][j][c] = 0.0f;

    const uint4 z4 = make_uint4(0u, 0u, 0u, 0u);

    for (int k0 = 0; k0 < K; k0 += 32) {
        // ---- stage tiles: 128 rows x 32 k per operand, hi+lo ----
        #pragma unroll
        for (int it = 0; it < 2; it++) {
            int idx = t + it * 256;           // 0..511
            int r   = idx >> 2;               // 0..127
            int c8  = (idx & 3) * 8;          // 0,8,16,24
            int gk  = k0 + c8;
            bool kok = (gk < K);              // K % 8 == 0 always
            // A
            uint4 vh = z4, vl = z4;
            int ga = m0 + r;
            if (ga < M && kok) {
                vh = *reinterpret_cast<const uint4*>(Ahi + (size_t)ga * lda + gk);
                vl = *reinterpret_cast<const uint4*>(Alo + (size_t)ga * lda + gk);
            }
            *reinterpret_cast<uint4*>(&AsH[r * SSTR + c8]) = vh;
            *reinterpret_cast<uint4*>(&AsL[r * SSTR + c8]) = vl;
            // B
            uint4 wh = z4, wl = z4;
            int gb = n0 + r;
            if (gb < N && kok) {
                wh = *reinterpret_cast<const uint4*>(Bhi + (size_t)gb * ldb + gk);
                wl = *reinterpret_cast<const uint4*>(Blo + (size_t)gb * ldb + gk);
            }
            *reinterpret_cast<uint4*>(&BsH[r * SSTR + c8]) = wh;
            *reinterpret_cast<uint4*>(&BsL[r * SSTR + c8]) = wl;
        }
        __syncthreads();

        #pragma unroll
        for (int ks = 0; ks < 32; ks += 16) {
            uint32_t ah[4][4], al[4][4], bh[4][2], bl[4][2];
            #pragma unroll
            for (int i = 0; i < 4; i++) {
                int ra = wm + i * 16;
                int o0 = (ra + g)     * SSTR + ks + 2 * tg;
                int o1 = (ra + g + 8) * SSTR + ks + 2 * tg;
                ah[i][0] = *reinterpret_cast<const uint32_t*>(&AsH[o0]);
                ah[i][1] = *reinterpret_cast<const uint32_t*>(&AsH[o1]);
                ah[i][2] = *reinterpret_cast<const uint32_t*>(&AsH[o0 + 8]);
                ah[i][3] = *reinterpret_cast<const uint32_t*>(&AsH[o1 + 8]);
                al[i][0] = *reinterpret_cast<const uint32_t*>(&AsL[o0]);
                al[i][1] = *reinterpret_cast<const uint32_t*>(&AsL[o1]);
                al[i][2] = *reinterpret_cast<const uint32_t*>(&AsL[o0 + 8]);
                al[i][3] = *reinterpret_cast<const uint32_t*>(&AsL[o1 + 8]);
            }
            #pragma unroll
            for (int j = 0; j < 4; j++) {
                int rb = wn + j * 8 + g;
                int o  = rb * SSTR + ks + 2 * tg;
                bh[j][0] = *reinterpret_cast<const uint32_t*>(&BsH[o]);
                bh[j][1] = *reinterpret_cast<const uint32_t*>(&BsH[o + 8]);
                bl[j][0] = *reinterpret_cast<const uint32_t*>(&BsL[o]);
                bl[j][1] = *reinterpret_cast<const uint32_t*>(&BsL[o + 8]);
            }
            #pragma unroll
            for (int i = 0; i < 4; i++)
                #pragma unroll
                for (int j = 0; j < 4; j++) {
                    mma16816(acc[i][j], ah[i], bh[j]);
                    mma16816(acc[i][j], ah[i], bl[j]);
                    mma16816(acc[i][j], al[i], bh[j]);
                }
        }
        __syncthreads();
    }

    // ---- epilogue ----
    #pragma unroll
    for (int i = 0; i < 4; i++) {
        #pragma unroll
        for (int j = 0; j < 4; j++) {
            int cn = n0 + wn + j * 8 + 2 * tg;
            if (cn >= N) continue;                 // N even -> cn+1 ok too
            #pragma unroll
            for (int h = 0; h < 2; h++) {          // two row halves g / g+8
                int rm = m0 + wm + i * 16 + g + h * 8;
                if (rm >= M) continue;
                float v0 = acc[i][j][2 * h + 0];
                float v1 = acc[i][j][2 * h + 1];
                if (ACT == 1) { v0 = tanhf(v0); v1 = tanhf(v1); }
                else if (ACT == 2) {
                    v0 = 1.0f / (1.0f + expf(-v0));
                    v1 = 1.0f / (1.0f + expf(-v1));
                }
                C[(size_t)rm * ldc + cn]     = v0;
                C[(size_t)rm * ldc + cn + 1] = v1;
                if (WSPLIT) {
                    __nv_bfloat16 hh, ll;
                    split2(v0, hh, ll);
                    Shi[(size_t)rm * lds + cn] = hh;
                    Slo[(size_t)rm * lds + cn] = ll;
                    split2(v1, hh, ll);
                    Shi[(size_t)rm * lds + cn + 1] = hh;
                    Slo[(size_t)rm * lds + cn + 1] = ll;
                }
            }
        }
    }
}

// ---------------- small fp32 SIMT GEMM (NN, no act) for X @ W ---------------
#define BM 128
#define BN 128
#define BK 8
__global__ __launch_bounds__(256) void simt_gemm(
    const float* __restrict__ A, const float* __restrict__ B,
    float* __restrict__ C, int M, int N, int K)
{
    __shared__ float As[BK][BM];
    __shared__ float Bs[BK][BN];
    const int t  = threadIdx.x;
    const int m0 = blockIdx.y * BM;
    const int n0 = blockIdx.x * BN;
    const int ar = t >> 1, ac = (t & 1) * 4;
    const int br = t >> 5, bc = (t & 31) * 4;
    const int ty = t >> 4, tx = t & 15;

    float acc[8][8];
    #pragma unroll
    for (int i = 0; i < 8; i++)
        #pragma unroll
        for (int j = 0; j < 8; j++) acc[i][j] = 0.0f;

    for (int k0 = 0; k0 < K; k0 += BK) {
        float4 av = make_float4(0.f, 0.f, 0.f, 0.f);
        if (m0 + ar < M && k0 + ac < K)
            av = *reinterpret_cast<const float4*>(A + (size_t)(m0 + ar) * K + k0 + ac);
        As[ac + 0][ar] = av.x; As[ac + 1][ar] = av.y;
        As[ac + 2][ar] = av.z; As[ac + 3][ar] = av.w;
        float4 bv = make_float4(0.f, 0.f, 0.f, 0.f);
        if (k0 + br < K && n0 + bc < N)
            bv = *reinterpret_cast<const float4*>(B + (size_t)(k0 + br) * N + n0 + bc);
        *reinterpret_cast<float4*>(&Bs[br][bc]) = bv;
        __syncthreads();
        #pragma unroll
        for (int kk = 0; kk < BK; kk++) {
            float a[8], b[8];
            *reinterpret_cast<float4*>(&a[0]) = *reinterpret_cast<const float4*>(&As[kk][ty * 8]);
            *reinterpret_cast<float4*>(&a[4]) = *reinterpret_cast<const float4*>(&As[kk][ty * 8 + 4]);
            *reinterpret_cast<float4*>(&b[0]) = *reinterpret_cast<const float4*>(&Bs[kk][tx * 8]);
            *reinterpret_cast<float4*>(&b[4]) = *reinterpret_cast<const float4*>(&Bs[kk][tx * 8 + 4]);
            #pragma unroll
            for (int i = 0; i < 8; i++)
                #pragma unroll
                for (int j = 0; j < 8; j++)
                    acc[i][j] = fmaf(a[i], b[j], acc[i][j]);
        }
        __syncthreads();
    }
    #pragma unroll
    for (int i = 0; i < 8; i++) {
        int m = m0 + ty * 8 + i;
        if (m >= M) continue;
        #pragma unroll
        for (int j = 0; j < 8; j++) {
            int n = n0 + tx * 8 + j;
            if (n < N) C[(size_t)m * N + n] = acc[i][j];
        }
    }
}

// ---------------- driver -----------------------------------------------------
extern "C" void kernel_launch(void* const* d_in, const int* in_sizes, int n_in,
                              void* d_out, int out_size)
{
    const float* z_igae = (const float*)d_in[0];  // [10000, 20]
    const float* adj    = (const float*)d_in[1];  // [10000, 10000]
    const float* w3     = (const float*)d_in[2];  // [20, 256]
    const float* w4     = (const float*)d_in[3];  // [256, 128]
    const float* w5     = (const float*)d_in[4];  // [128, 500]

    float* out      = (float*)d_out;
    float* z_hat    = out;                          // [10000, 500]
    float* z_hatadj = out + (size_t)NROWS * 500;    // [10000, 10000]

    __nv_bfloat16 *adjH, *adjL, *btH, *btL, *zhH, *zhL;
    float *f1, *f2;
    cudaGetSymbolAddress((void**)&adjH, g_adj_hi);
    cudaGetSymbolAddress((void**)&adjL, g_adj_lo);
    cudaGetSymbolAddress((void**)&btH,  g_bt_hi);
    cudaGetSymbolAddress((void**)&btL,  g_bt_lo);
    cudaGetSymbolAddress((void**)&zhH,  g_zh_hi);
    cudaGetSymbolAddress((void**)&zhL,  g_zh_lo);
    cudaGetSymbolAddress((void**)&f1,   g_f1);
    cudaGetSymbolAddress((void**)&f2,   g_f2);

    // 0. split adj -> bf16 hi/lo
    {
        int n4 = (int)(ADJ_N / 4);
        split_vec4<<<(n4 + 255) / 256, 256>>>(adj, adjH, adjL, n4);
    }

    dim3 blk(256);

    // 1. T1 = z_igae @ w3  [10000,256]
    simt_gemm<<<dim3(2, 79), blk>>>(z_igae, w3, f1, NROWS, 256, 20);
    // 2. transpose+split T1 -> [256,10000]
    tsplit_kernel<<<dim3(8, 313), blk>>>(f1, NROWS, 256, btH, btL);
    // 3. Z1 = tanh(adj @ T1)  [10000,256]
    mma_gemm<1, 0><<<dim3(2, 79), blk>>>(adjH, adjL, NROWS, btH, btL, NROWS,
                                         f2, 256, nullptr, nullptr, 0,
                                         NROWS, 256, NROWS);
    // 4. T2 = Z1 @ w4  [10000,128]
    simt_gemm<<<dim3(1, 79), blk>>>(f2, w4, f1, NROWS, 128, 256);
    // 5. transpose+split T2 -> [128,10000]
    tsplit_kernel<<<dim3(4, 313), blk>>>(f1, NROWS, 128, btH, btL);
    // 6. Z2 = tanh(adj @ T2)  [10000,128]
    mma_gemm<1, 0><<<dim3(1, 79), blk>>>(adjH, adjL, NROWS, btH, btL, NROWS,
                                         f2, 128, nullptr, nullptr, 0,
                                         NROWS, 128, NROWS);
    // 7. T3 = Z2 @ w5  [10000,500]
    simt_gemm<<<dim3(4, 79), blk>>>(f2, w5, f1, NROWS, 500, 128);
    // 8. transpose+split T3 -> [500,10000]
    tsplit_kernel<<<dim3(16, 313), blk>>>(f1, NROWS, 500, btH, btL);
    // 9. z_hat = adj @ T3  [10000,500], fused bf16 split (lds=512, pads stay 0)
    mma_gemm<0, 1><<<dim3(4, 79), blk>>>(adjH, adjL, NROWS, btH, btL, NROWS,
                                         z_hat, 500, zhH, zhL, 512,
                                         NROWS, 500, NROWS);
    // 10. z_hat_adj = sigmoid(z_hat @ z_hat^T)  [10000,10000], K padded 512
    mma_gemm<2, 0><<<dim3(79, 79), blk>>>(zhH, zhL, 512, zhH, zhL, 512,
                                          z_hatadj, NROWS, nullptr, nullptr, 0,
                                          NROWS, NROWS, 512);
}

// round 3
// speedup vs baseline: 3.1788x; 1.4909x over previous
#include <cuda_runtime.h>
#include <cuda_bf16.h>
#include <math.h>
#include <stdint.h>

// ============================================================================
// GCN decoder chain. Big GEMMs on tensor cores via mma.sync m16n8k16 bf16 with
// 2-term splitting (C = Ahi*Bhi + Ahi*Blo + Alo*Bhi). Round 3: cp.async
// double-buffered mainloop, ldmatrix fragment loads, symmetric-SYRK mirroring.
// ============================================================================

#define NROWS 10000
#define ADJ_N 100000000LL
#define SSTR 40                       // smem k-stride (bf16), conflict-free
#define ARR_BYTES (128 * SSTR * 2)    // 10240 per operand array
#define STAGE_BYTES (4 * ARR_BYTES)   // 40960 per stage (AH, AL, BH, BL)
#define SMEM_BYTES (2 * STAGE_BYTES)  // 81920 (also >= 128*132*4 mirror tile)

// ---------------- scratch (static __device__, allocation-free) -------------
__device__ __nv_bfloat16 g_adj_hi[100000000];
__device__ __nv_bfloat16 g_adj_lo[100000000];
__device__ __nv_bfloat16 g_bt_hi[500 * 10000];
__device__ __nv_bfloat16 g_bt_lo[500 * 10000];
__device__ __nv_bfloat16 g_zh_hi[10000 * 512];   // pads (cols 500..511) stay 0
__device__ __nv_bfloat16 g_zh_lo[10000 * 512];
__device__ float g_f1[10000 * 512];
__device__ float g_f2[10000 * 512];

// ---------------- helpers ----------------------------------------------------
__device__ __forceinline__ void split2(float x, __nv_bfloat16& h, __nv_bfloat16& l) {
    h = __float2bfloat16(x);
    l = __float2bfloat16(x - __bfloat162float(h));
}

__device__ __forceinline__ void cp16(uint32_t daddr, const void* src, int ok) {
    int sz = ok ? 16 : 0;
    asm volatile("cp.async.cg.shared.global [%0], [%1], 16, %2;"
                 :: "r"(daddr), "l"(src), "r"(sz));
}
__device__ __forceinline__ void cp_commit() {
    asm volatile("cp.async.commit_group;");
}
__device__ __forceinline__ void cp_wait1() {
    asm volatile("cp.async.wait_group 1;");
}
__device__ __forceinline__ void ldsm4(uint32_t& r0, uint32_t& r1, uint32_t& r2,
                                      uint32_t& r3, uint32_t addr) {
    asm volatile("ldmatrix.sync.aligned.m8n8.x4.shared.b16 {%0,%1,%2,%3}, [%4];"
                 : "=r"(r0), "=r"(r1), "=r"(r2), "=r"(r3) : "r"(addr));
}
__device__ __forceinline__ void mma16816(float c[4], const uint32_t a[4],
                                         const uint32_t b[2]) {
    asm volatile(
        "mma.sync.aligned.m16n8k16.row.col.f32.bf16.bf16.f32 "
        "{%0,%1,%2,%3}, {%4,%5,%6,%7}, {%8,%9}, {%0,%1,%2,%3};"
        : "+f"(c[0]), "+f"(c[1]), "+f"(c[2]), "+f"(c[3])
        : "r"(a[0]), "r"(a[1]), "r"(a[2]), "r"(a[3]), "r"(b[0]), "r"(b[1]));
}

// ---------------- adj split (elementwise, float4) ---------------------------
__global__ void split_vec4(const float* __restrict__ x,
                           __nv_bfloat16* __restrict__ hi,
                           __nv_bfloat16* __restrict__ lo, int n4)
{
    int i = blockIdx.x * blockDim.x + threadIdx.x;
    if (i >= n4) return;
    float4 v = reinterpret_cast<const float4*>(x)[i];
    __nv_bfloat16 h0, h1, h2, h3, l0, l1, l2, l3;
    split2(v.x, h0, l0); split2(v.y, h1, l1);
    split2(v.z, h2, l2); split2(v.w, h3, l3);
    reinterpret_cast<__nv_bfloat162*>(hi)[2 * i + 0] = __halves2bfloat162(h0, h1);
    reinterpret_cast<__nv_bfloat162*>(hi)[2 * i + 1] = __halves2bfloat162(h2, h3);
    reinterpret_cast<__nv_bfloat162*>(lo)[2 * i + 0] = __halves2bfloat162(l0, l1);
    reinterpret_cast<__nv_bfloat162*>(lo)[2 * i + 1] = __halves2bfloat162(l2, l3);
}

// ---------------- transpose + split: T[Kt,Nn] fp32 -> hi/lo [Nn,Kt] bf16 ----
__global__ void tsplit_kernel(const float* __restrict__ T, int Kt, int Nn,
                              __nv_bfloat16* __restrict__ hi,
                              __nv_bfloat16* __restrict__ lo)
{
    __shared__ float sm[32][33];
    int tx = threadIdx.x & 31;
    int ty = threadIdx.x >> 5;
    int k0 = blockIdx.y * 32;
    int n0 = blockIdx.x * 32;
    #pragma unroll
    for (int r = 0; r < 4; r++) {
        int row = k0 + ty + r * 8;
        int col = n0 + tx;
        sm[ty + r * 8][tx] = (row < Kt && col < Nn) ? T[(size_t)row * Nn + col] : 0.0f;
    }
    __syncthreads();
    #pragma unroll
    for (int r = 0; r < 4; r++) {
        int n = n0 + ty + r * 8;
        int k = k0 + tx;
        if (n < Nn && k < Kt) {
            float v = sm[tx][ty + r * 8];
            __nv_bfloat16 h, l;
            split2(v, h, l);
            hi[(size_t)n * Kt + k] = h;
            lo[(size_t)n * Kt + k] = l;
        }
    }
}

// ---------------- tensor-core split-bf16 GEMM -------------------------------
// C[M,N] = A[M,K] @ B[N,K]^T. ACT: 0 none, 1 tanh, 2 sigmoid.
// WSPLIT: also write bf16 split of C. MIRROR: triangular grid + symmetric
// mirror store (requires M == N, A == B semantics).
template <int ACT, int WSPLIT, int MIRROR>
__global__ __launch_bounds__(256, 1) void mma_gemm(
    const __nv_bfloat16* __restrict__ Ahi, const __nv_bfloat16* __restrict__ Alo, int lda,
    const __nv_bfloat16* __restrict__ Bhi, const __nv_bfloat16* __restrict__ Blo, int ldb,
    float* __restrict__ C, int ldc,
    __nv_bfloat16* __restrict__ Shi, __nv_bfloat16* __restrict__ Slo, int lds,
    int M, int N, int K)
{
    extern __shared__ char smem[];

    const int t    = threadIdx.x;
    const int lane = t & 31;
    const int wid  = t >> 5;
    const int wm   = (wid >> 2) * 64;
    const int wn   = (wid & 3) * 32;
    const int g    = lane >> 2;
    const int tg   = lane & 3;

    int bx, by;
    if (MIRROR) {
        int bid = blockIdx.x;
        by = (int)((sqrtf(8.0f * (float)bid + 1.0f) - 1.0f) * 0.5f);
        while ((by + 1) * (by + 2) / 2 <= bid) by++;
        while (by * (by + 1) / 2 > bid) by--;
        bx = bid - by * (by + 1) / 2;
    } else {
        bx = blockIdx.x;
        by = blockIdx.y;
    }
    const int m0 = by * 128;
    const int n0 = bx * 128;

    float acc[4][4][4];
    #pragma unroll
    for (int i = 0; i < 4; i++)
        #pragma unroll
        for (int j = 0; j < 4; j++)
            #pragma unroll
            for (int c = 0; c < 4; c++) acc[i][j][c] = 0.0f;

    // loader indices: 256 threads * 2 iters -> (row 0..127, chunk 0..3)
    const int lr0 = t >> 2;
    const int lc0 = (t & 3) * 8;

    // ldmatrix lane addressing
    const int a_row = lane & 15;              // row within 16-row frag
    const int a_c8  = (lane >> 4) * 8;        // k offset 0/8
    const int b_row = (lane & 7) + ((lane >> 4) << 3);
    const int b_c8  = ((lane >> 3) & 1) * 8;

    const int ntiles = (K + 31) / 32;

    // ---- stage loader (cp.async) ----
    auto load_stage = [&](int s, int k0) {
        char* sb = smem + s * STAGE_BYTES;
        #pragma unroll
        for (int it = 0; it < 2; it++) {
            int r   = lr0 + it * 64;
            int c8  = lc0;
            int gk  = k0 + c8;
            int kok = (gk < K);
            int ga  = m0 + r;
            int aok = kok && (ga < M);
            int gb  = n0 + r;
            int bok = kok && (gb < N);
            size_t aoff = aok ? ((size_t)ga * lda + gk) : 0;
            size_t boff = bok ? ((size_t)gb * ldb + gk) : 0;
            uint32_t so = (uint32_t)(r * SSTR + c8) * 2;
            uint32_t base = (uint32_t)__cvta_generic_to_shared(sb);
            cp16(base + 0 * ARR_BYTES + so, Ahi + aoff, aok);
            cp16(base + 1 * ARR_BYTES + so, Alo + aoff, aok);
            cp16(base + 2 * ARR_BYTES + so, Bhi + boff, bok);
            cp16(base + 3 * ARR_BYTES + so, Blo + boff, bok);
        }
    };

    load_stage(0, 0);
    cp_commit();

    int s = 0;
    for (int kt = 0; kt < ntiles; kt++) {
        __syncthreads();                  // stage s^1 consumers from prev iter done
        load_stage(s ^ 1, (kt + 1) * 32); // zero-fills / preds handle the tail
        cp_commit();
        cp_wait1();                       // stage s data landed
        __syncthreads();

        const char* sb = smem + s * STAGE_BYTES;
        const __nv_bfloat16* sAH = (const __nv_bfloat16*)(sb);
        const __nv_bfloat16* sAL = (const __nv_bfloat16*)(sb + ARR_BYTES);
        const __nv_bfloat16* sBH = (const __nv_bfloat16*)(sb + 2 * ARR_BYTES);
        const __nv_bfloat16* sBL = (const __nv_bfloat16*)(sb + 3 * ARR_BYTES);

        #pragma unroll
        for (int ks = 0; ks < 32; ks += 16) {
            uint32_t ah[4][4], al[4][4], bh[2][4], bl[2][4];
            #pragma unroll
            for (int i = 0; i < 4; i++) {
                int off = (wm + i * 16 + a_row) * SSTR + ks + a_c8;
                ldsm4(ah[i][0], ah[i][1], ah[i][2], ah[i][3],
                      (uint32_t)__cvta_generic_to_shared(sAH + off));
                ldsm4(al[i][0], al[i][1], al[i][2], al[i][3],
                      (uint32_t)__cvta_generic_to_shared(sAL + off));
            }
            #pragma unroll
            for (int jp = 0; jp < 2; jp++) {
                int off = (wn + jp * 16 + b_row) * SSTR + ks + b_c8;
                ldsm4(bh[jp][0], bh[jp][1], bh[jp][2], bh[jp][3],
                      (uint32_t)__cvta_generic_to_shared(sBH + off));
                ldsm4(bl[jp][0], bl[jp][1], bl[jp][2], bl[jp][3],
                      (uint32_t)__cvta_generic_to_shared(sBL + off));
            }
            #pragma unroll
            for (int i = 0; i < 4; i++)
                #pragma unroll
                for (int j = 0; j < 4; j++) {
                    const uint32_t* bhj = &bh[j >> 1][(j & 1) * 2];
                    const uint32_t* blj = &bl[j >> 1][(j & 1) * 2];
                    mma16816(acc[i][j], ah[i], bhj);
                    mma16816(acc[i][j], ah[i], blj);
                    mma16816(acc[i][j], al[i], bhj);
                }
        }
        s ^= 1;
    }

    const bool do_mirror = MIRROR && (bx != by);
    float* tile = (float*)smem;       // 128 x 132 fp32, aliases stage buffers
    if (do_mirror) __syncthreads();   // mainloop smem reads done before overwrite

    // ---- epilogue ----
    #pragma unroll
    for (int i = 0; i < 4; i++) {
        #pragma unroll
        for (int j = 0; j < 4; j++) {
            int nl = wn + j * 8 + 2 * tg;
            int cn = n0 + nl;
            if (cn >= N) continue;
            #pragma unroll
            for (int h = 0; h < 2; h++) {
                int ml = wm + i * 16 + g + h * 8;
                int rm = m0 + ml;
                if (rm >= M) continue;
                float v0 = acc[i][j][2 * h + 0];
                float v1 = acc[i][j][2 * h + 1];
                if (ACT == 1) { v0 = tanhf(v0); v1 = tanhf(v1); }
                else if (ACT == 2) {
                    v0 = 1.0f / (1.0f + expf(-v0));
                    v1 = 1.0f / (1.0f + expf(-v1));
                }
                C[(size_t)rm * ldc + cn]     = v0;
                C[(size_t)rm * ldc + cn + 1] = v1;
                if (do_mirror) {
                    tile[(nl + 0) * 132 + ml] = v0;
                    tile[(nl + 1) * 132 + ml] = v1;
                }
                if (WSPLIT) {
                    __nv_bfloat16 hh, ll;
                    split2(v0, hh, ll);
                    Shi[(size_t)rm * lds + cn] = hh;
                    Slo[(size_t)rm * lds + cn] = ll;
                    split2(v1, hh, ll);
                    Shi[(size_t)rm * lds + cn + 1] = hh;
                    Slo[(size_t)rm * lds + cn + 1] = ll;
                }
            }
        }
    }

    if (do_mirror) {
        __syncthreads();
        // write block (bx,by): C[n0+r][m0+c] = tile[r][c], coalesced
        for (int i = t; i < 128 * 32; i += 256) {
            int r  = i >> 5;
            int c4 = (i & 31) * 4;
            int gr = n0 + r;
            int gc = m0 + c4;
            if (gr < N && gc < M) {
                float4 v = *reinterpret_cast<const float4*>(&tile[r * 132 + c4]);
                *reinterpret_cast<float4*>(&C[(size_t)gr * ldc + gc]) = v;
            }
        }
    }
}

// ---------------- small fp32 SIMT GEMM (NN, no act) for X @ W ---------------
#define BM 128
#define BN 128
#define BK 8
__global__ __launch_bounds__(256) void simt_gemm(
    const float* __restrict__ A, const float* __restrict__ B,
    float* __restrict__ C, int M, int N, int K)
{
    __shared__ float As[BK][BM];
    __shared__ float Bs[BK][BN];
    const int t  = threadIdx.x;
    const int m0 = blockIdx.y * BM;
    const int n0 = blockIdx.x * BN;
    const int ar = t >> 1, ac = (t & 1) * 4;
    const int br = t >> 5, bc = (t & 31) * 4;
    const int ty = t >> 4, tx = t & 15;

    float acc[8][8];
    #pragma unroll
    for (int i = 0; i < 8; i++)
        #pragma unroll
        for (int j = 0; j < 8; j++) acc[i][j] = 0.0f;

    for (int k0 = 0; k0 < K; k0 += BK) {
        float4 av = make_float4(0.f, 0.f, 0.f, 0.f);
        if (m0 + ar < M && k0 + ac < K)
            av = *reinterpret_cast<const float4*>(A + (size_t)(m0 + ar) * K + k0 + ac);
        As[ac + 0][ar] = av.x; As[ac + 1][ar] = av.y;
        As[ac + 2][ar] = av.z; As[ac + 3][ar] = av.w;
        float4 bv = make_float4(0.f, 0.f, 0.f, 0.f);
        if (k0 + br < K && n0 + bc < N)
            bv = *reinterpret_cast<const float4*>(B + (size_t)(k0 + br) * N + n0 + bc);
        *reinterpret_cast<float4*>(&Bs[br][bc]) = bv;
        __syncthreads();
        #pragma unroll
        for (int kk = 0; kk < BK; kk++) {
            float a[8], b[8];
            *reinterpret_cast<float4*>(&a[0]) = *reinterpret_cast<const float4*>(&As[kk][ty * 8]);
            *reinterpret_cast<float4*>(&a[4]) = *reinterpret_cast<const float4*>(&As[kk][ty * 8 + 4]);
            *reinterpret_cast<float4*>(&b[0]) = *reinterpret_cast<const float4*>(&Bs[kk][tx * 8]);
            *reinterpret_cast<float4*>(&b[4]) = *reinterpret_cast<const float4*>(&Bs[kk][tx * 8 + 4]);
            #pragma unroll
            for (int i = 0; i < 8; i++)
                #pragma unroll
                for (int j = 0; j < 8; j++)
                    acc[i][j] = fmaf(a[i], b[j], acc[i][j]);
        }
        __syncthreads();
    }
    #pragma unroll
    for (int i = 0; i < 8; i++) {
        int m = m0 + ty * 8 + i;
        if (m >= M) continue;
        #pragma unroll
        for (int j = 0; j < 8; j++) {
            int n = n0 + tx * 8 + j;
            if (n < N) C[(size_t)m * N + n] = acc[i][j];
        }
    }
}

// ---------------- driver -----------------------------------------------------
extern "C" void kernel_launch(void* const* d_in, const int* in_sizes, int n_in,
                              void* d_out, int out_size)
{
    const float* z_igae = (const float*)d_in[0];  // [10000, 20]
    const float* adj    = (const float*)d_in[1];  // [10000, 10000]
    const float* w3     = (const float*)d_in[2];  // [20, 256]
    const float* w4     = (const float*)d_in[3];  // [256, 128]
    const float* w5     = (const float*)d_in[4];  // [128, 500]

    float* out      = (float*)d_out;
    float* z_hat    = out;                          // [10000, 500]
    float* z_hatadj = out + (size_t)NROWS * 500;    // [10000, 10000]

    __nv_bfloat16 *adjH, *adjL, *btH, *btL, *zhH, *zhL;
    float *f1, *f2;
    cudaGetSymbolAddress((void**)&adjH, g_adj_hi);
    cudaGetSymbolAddress((void**)&adjL, g_adj_lo);
    cudaGetSymbolAddress((void**)&btH,  g_bt_hi);
    cudaGetSymbolAddress((void**)&btL,  g_bt_lo);
    cudaGetSymbolAddress((void**)&zhH,  g_zh_hi);
    cudaGetSymbolAddress((void**)&zhL,  g_zh_lo);
    cudaGetSymbolAddress((void**)&f1,   g_f1);
    cudaGetSymbolAddress((void**)&f2,   g_f2);

    cudaFuncSetAttribute(mma_gemm<1, 0, 0>,
                         cudaFuncAttributeMaxDynamicSharedMemorySize, SMEM_BYTES);
    cudaFuncSetAttribute(mma_gemm<0, 1, 0>,
                         cudaFuncAttributeMaxDynamicSharedMemorySize, SMEM_BYTES);
    cudaFuncSetAttribute(mma_gemm<2, 0, 1>,
                         cudaFuncAttributeMaxDynamicSharedMemorySize, SMEM_BYTES);

    // 0. split adj -> bf16 hi/lo
    {
        int n4 = (int)(ADJ_N / 4);
        split_vec4<<<(n4 + 255) / 256, 256>>>(adj, adjH, adjL, n4);
    }

    dim3 blk(256);

    // 1. T1 = z_igae @ w3  [10000,256]
    simt_gemm<<<dim3(2, 79), blk>>>(z_igae, w3, f1, NROWS, 256, 20);
    // 2. transpose+split T1 -> [256,10000]
    tsplit_kernel<<<dim3(8, 313), blk>>>(f1, NROWS, 256, btH, btL);
    // 3. Z1 = tanh(adj @ T1)  [10000,256]
    mma_gemm<1, 0, 0><<<dim3(2, 79), blk, SMEM_BYTES>>>(
        adjH, adjL, NROWS, btH, btL, NROWS,
        f2, 256, nullptr, nullptr, 0, NROWS, 256, NROWS);
    // 4. T2 = Z1 @ w4  [10000,128]
    simt_gemm<<<dim3(1, 79), blk>>>(f2, w4, f1, NROWS, 128, 256);
    // 5. transpose+split T2 -> [128,10000]
    tsplit_kernel<<<dim3(4, 313), blk>>>(f1, NROWS, 128, btH, btL);
    // 6. Z2 = tanh(adj @ T2)  [10000,128]
    mma_gemm<1, 0, 0><<<dim3(1, 79), blk, SMEM_BYTES>>>(
        adjH, adjL, NROWS, btH, btL, NROWS,
        f2, 128, nullptr, nullptr, 0, NROWS, 128, NROWS);
    // 7. T3 = Z2 @ w5  [10000,500]
    simt_gemm<<<dim3(4, 79), blk>>>(f2, w5, f1, NROWS, 500, 128);
    // 8. transpose+split T3 -> [500,10000]
    tsplit_kernel<<<dim3(16, 313), blk>>>(f1, NROWS, 500, btH, btL);
    // 9. z_hat = adj @ T3  [10000,500], fused bf16 split (lds=512, pads stay 0)
    mma_gemm<0, 1, 0><<<dim3(4, 79), blk, SMEM_BYTES>>>(
        adjH, adjL, NROWS, btH, btL, NROWS,
        z_hat, 500, zhH, zhL, 512, NROWS, 500, NROWS);
    // 10. z_hat_adj = sigmoid(z_hat @ z_hat^T): symmetric -> triangular grid
    {
        int nblk = 79 * 80 / 2;  // 3160
        mma_gemm<2, 0, 1><<<dim3(nblk), blk, SMEM_BYTES>>>(
            zhH, zhL, 512, zhH, zhL, 512,
            z_hatadj, NROWS, nullptr, nullptr, 0, NROWS, NROWS, 512);
    }
}